// round 3
// baseline (speedup 1.0000x reference)
#include <cuda_runtime.h>
#include <cstdint>
#include <math.h>

#define NB 1024
#define NS 256
#define ND 64
#define NH 128
#define NG 512
#define KHS 96          // W_hh rows cached in smem

// -------- static scratch (no allocations allowed) --------
__device__ float      g_x_pre[(size_t)NB * NS * NG];   // 512 MB: x@W_ih + b, [b][s][g]
__device__ float      g_seq_h[(size_t)NB * NS * NH];   // 128 MB: h for every (b,s)
__device__ ulonglong2 g_WtHH[NH * NH];                 // W_hh gate-interleaved pairs

// -------- packed f32x2 helpers --------
__device__ __forceinline__ unsigned long long pack2(float lo, float hi) {
    unsigned long long d;
    asm("mov.b64 %0, {%1, %2};" : "=l"(d) : "f"(lo), "f"(hi));
    return d;
}
__device__ __forceinline__ float2 unpack2(unsigned long long v) {
    float2 r;
    asm("mov.b64 {%0, %1}, %2;" : "=f"(r.x), "=f"(r.y) : "l"(v));
    return r;
}
__device__ __forceinline__ unsigned long long fma2(unsigned long long a,
                                                   unsigned long long b,
                                                   unsigned long long c) {
    unsigned long long d;
    asm("fma.rn.f32x2 %0, %1, %2, %3;" : "=l"(d) : "l"(a), "l"(b), "l"(c));
    return d;
}

__device__ __forceinline__ float gelu_exact(float x) {
    return 0.5f * x * (1.0f + erff(x * 0.7071067811865476f));
}

// ============ kernel 0: gate-interleave W_hh ============
// out[k][j] = { pack(W[k][j], W[k][128+j]), pack(W[k][256+j], W[k][384+j]) }
__global__ void k_pack_whh(const float* __restrict__ W_hh) {
    int k = blockIdx.x, j = threadIdx.x;
    const float* w = W_hh + k * NG + j;
    g_WtHH[k * NH + j] =
        make_ulonglong2(pack2(w[0], w[NH]), pack2(w[2 * NH], w[3 * NH]));
}

// ============ kernel 1: x_pre = x @ W_ih + b_cell ============
// CTA: 256 threads, 16 (b,s)-rows, each thread 2 cols x 16 rows via fma2 row pairs.
__global__ void __launch_bounds__(256) k_xpre(const float* __restrict__ x,
                                              const float* __restrict__ W_ih,
                                              const float* __restrict__ b_cell) {
    __shared__ unsigned long long xs2[8][ND];  // {row 2r, row 2r+1} pairs
    int t = threadIdx.x;
    int row0 = blockIdx.x * 16;

    for (int idx = t; idx < 8 * ND; idx += 256) {
        int r2 = idx >> 6, d = idx & 63;
        xs2[r2][d] = pack2(x[(row0 + 2 * r2) * ND + d],
                           x[(row0 + 2 * r2 + 1) * ND + d]);
    }
    __syncthreads();

    int c0 = t, c1 = t + 256;
    unsigned long long acc0[8], acc1[8];
    unsigned long long b0d = pack2(b_cell[c0], b_cell[c0]);
    unsigned long long b1d = pack2(b_cell[c1], b_cell[c1]);
#pragma unroll
    for (int r2 = 0; r2 < 8; r2++) { acc0[r2] = b0d; acc1[r2] = b1d; }

#pragma unroll 8
    for (int d = 0; d < ND; d++) {
        float w0 = W_ih[d * NG + c0];
        float w1 = W_ih[d * NG + c1];
        unsigned long long w0d = pack2(w0, w0);
        unsigned long long w1d = pack2(w1, w1);
#pragma unroll
        for (int r2 = 0; r2 < 8; r2++) {
            unsigned long long xv = xs2[r2][d];
            acc0[r2] = fma2(xv, w0d, acc0[r2]);
            acc1[r2] = fma2(xv, w1d, acc1[r2]);
        }
    }
#pragma unroll
    for (int r2 = 0; r2 < 8; r2++) {
        float2 v0 = unpack2(acc0[r2]);
        float2 v1 = unpack2(acc1[r2]);
        int ra = row0 + 2 * r2, rb = ra + 1;
        g_x_pre[(size_t)ra * NG + c0] = v0.x;
        g_x_pre[(size_t)rb * NG + c0] = v0.y;
        g_x_pre[(size_t)ra * NG + c1] = v1.x;
        g_x_pre[(size_t)rb * NG + c1] = v1.y;
    }
}

// ============ kernel 2: sLSTM scan ============
// 128 CTAs x 8 batch rows, 256 threads. Thread: gate column j for 4 rows.
__global__ void __launch_bounds__(256, 1) k_scan() {
    extern __shared__ unsigned char smraw[];
    ulonglong2* WhhS = (ulonglong2*)smraw;                           // KHS*128*16 B
    unsigned long long* h_s2 =
        (unsigned long long*)(smraw + (size_t)KHS * NH * 16);        // 8*128 dup pairs

    const int t  = threadIdx.x;
    const int j  = t & 127;
    const int rb = (t >> 7) << 2;  // 0 or 4
    const int b0 = blockIdx.x * 8;

    for (int idx = t; idx < KHS * NH; idx += 256) WhhS[idx] = g_WtHH[idx];
    for (int idx = t; idx < 8 * NH; idx += 256) h_s2[idx] = 0ull;

    float c[4] = {0.f, 0.f, 0.f, 0.f};
    float n[4] = {1.f, 1.f, 1.f, 1.f};

    const float* xr[4];
#pragma unroll
    for (int r = 0; r < 4; r++)
        xr[r] = g_x_pre + (size_t)(b0 + rb + r) * NS * NG + j;

    float xc[16], xn[16];
#pragma unroll
    for (int r = 0; r < 4; r++)
#pragma unroll
        for (int g = 0; g < 4; g++) xc[r * 4 + g] = xr[r][g * NH];

    __syncthreads();

    for (int s = 0; s < NS; ++s) {
        unsigned long long a01[4], a23[4];
#pragma unroll
        for (int r = 0; r < 4; r++) {
            a01[r] = pack2(xc[r * 4 + 0], xc[r * 4 + 1]);
            a23[r] = pack2(xc[r * 4 + 2], xc[r * 4 + 3]);
        }
        // prefetch next step's x_pre
        int sn = (s + 1 < NS) ? (s + 1) : s;
#pragma unroll
        for (int r = 0; r < 4; r++)
#pragma unroll
            for (int g = 0; g < 4; g++)
                xn[r * 4 + g] = xr[r][(size_t)sn * NG + g * NH];

        // smem-cached W_hh rows
#pragma unroll 4
        for (int k = 0; k < KHS; k += 2) {
            ulonglong2 w0 = WhhS[k * NH + j];
            ulonglong2 w1 = WhhS[(k + 1) * NH + j];
#pragma unroll
            for (int r = 0; r < 4; r++) {
                ulonglong2 hp = *(const ulonglong2*)&h_s2[(rb + r) * NH + k];
                a01[r] = fma2(hp.x, w0.x, a01[r]);
                a23[r] = fma2(hp.x, w0.y, a23[r]);
                a01[r] = fma2(hp.y, w1.x, a01[r]);
                a23[r] = fma2(hp.y, w1.y, a23[r]);
            }
        }
        // L2-streamed W_hh rows
#pragma unroll 4
        for (int k = KHS; k < NH; k += 2) {
            ulonglong2 w0 = g_WtHH[k * NH + j];
            ulonglong2 w1 = g_WtHH[(k + 1) * NH + j];
#pragma unroll
            for (int r = 0; r < 4; r++) {
                ulonglong2 hp = *(const ulonglong2*)&h_s2[(rb + r) * NH + k];
                a01[r] = fma2(hp.x, w0.x, a01[r]);
                a23[r] = fma2(hp.x, w0.y, a23[r]);
                a01[r] = fma2(hp.y, w1.x, a01[r]);
                a23[r] = fma2(hp.y, w1.y, a23[r]);
            }
        }

        float hnew[4];
#pragma unroll
        for (int r = 0; r < 4; r++) {
            float2 if_ = unpack2(a01[r]);
            float2 zo  = unpack2(a23[r]);
            float iv = expf(if_.x);
            float fv = 1.f / (1.f + expf(-if_.y));
            float zv = tanhf(zo.x);
            float ov = 1.f / (1.f + expf(-zo.y));
            c[r] = fv * c[r] + iv * zv;
            n[r] = fv * n[r] + iv;
            hnew[r] = ov * (c[r] / n[r]);
        }
        __syncthreads();
#pragma unroll
        for (int r = 0; r < 4; r++) {
            h_s2[(rb + r) * NH + j] = pack2(hnew[r], hnew[r]);
            g_seq_h[((size_t)(b0 + rb + r) * NS + s) * NH + j] = hnew[r];
        }
        __syncthreads();
#pragma unroll
        for (int i = 0; i < 16; i++) xc[i] = xn[i];
    }
}

// ============ kernel 3: attention (last row) + MLP head, one CTA per batch ============
#define SEQ_PS 257  // padded k-stride for transposed seq tile
__global__ void __launch_bounds__(128) k_final(
    const float* __restrict__ action, const float* __restrict__ info,
    const float* __restrict__ Wq, const float* __restrict__ Wk,
    const float* __restrict__ Wv, const float* __restrict__ Wo,
    const float* __restrict__ q_w1, const float* __restrict__ q_b1,
    const float* __restrict__ q_gamma, const float* __restrict__ q_beta,
    const float* __restrict__ q_w2, const float* __restrict__ q_b2,
    const float* __restrict__ q_w3, const float* __restrict__ q_b3,
    float* __restrict__ out) {
    extern __shared__ float sm[];
    float* seqT   = sm;                    // [128][257] transposed: seqT[m*257+k]
    float* scores = seqT + NH * SEQ_PS;    // [4][256]
    float* rbuf   = scores + 4 * NS;       // [4][128]
    float* ubuf   = rbuf + 4 * NH;         // [4][128]
    float* qlast  = ubuf + 4 * NH;         // [128]
    float* o1buf  = qlast + NH;            // [128]
    float* catb   = o1buf + NH;            // [144]
    float* red    = catb + 144;            // [128]
    float* red2   = red + NH;              // [128]
    float* hvb    = red2 + NH;             // [128]
    float* invs   = hvb + NH;              // [4]

    const int t = threadIdx.x;
    const int b = blockIdx.x;

    // stage seq_h[b] transposed (conflict-free: bank = (m+k)%32)
    const float* src = g_seq_h + (size_t)b * NS * NH;
    for (int i = t; i < NS * NH; i += 128) {
        int k = i >> 7, m = i & 127;
        seqT[m * SEQ_PS + k] = src[i];
    }
    __syncthreads();

    // q_last[j] = sum_k h_last[k] * Wq[k][j]
    {
        float acc = 0.f;
#pragma unroll 8
        for (int k = 0; k < NH; k++)
            acc += seqT[k * SEQ_PS + (NS - 1)] * Wq[k * NH + t];
        qlast[t] = acc;
    }
    __syncthreads();

    // r[h][m=t] = sum_d Wk[t][h*32+d] * qlast[h*32+d]
#pragma unroll
    for (int h = 0; h < 4; h++) {
        float acc = 0.f;
#pragma unroll 8
        for (int d = 0; d < 32; d++)
            acc += Wk[t * NH + h * 32 + d] * qlast[h * 32 + d];
        rbuf[h * NH + t] = acc;
    }
    __syncthreads();

    // scores[h][k] = (seq_h[b][k] . r[h]) / sqrt(32)
    const float is32 = 0.17677669529663687f;
#pragma unroll
    for (int h = 0; h < 4; h++) {
#pragma unroll
        for (int kk = 0; kk < 2; kk++) {
            int k = t + (kk << 7);
            float acc = 0.f;
#pragma unroll 8
            for (int m = 0; m < NH; m++)
                acc += seqT[m * SEQ_PS + k] * rbuf[h * NH + m];
            scores[h * NS + k] = acc * is32;
        }
    }
    __syncthreads();

    // softmax per head: warp h owns head h
    {
        int h = t >> 5, l = t & 31;
        float mx = -1e30f;
#pragma unroll
        for (int i = 0; i < 8; i++)
            mx = fmaxf(mx, scores[h * NS + l + 32 * i]);
#pragma unroll
        for (int o = 16; o > 0; o >>= 1)
            mx = fmaxf(mx, __shfl_xor_sync(0xffffffffu, mx, o));
        float sum = 0.f;
#pragma unroll
        for (int i = 0; i < 8; i++) {
            int idx = h * NS + l + 32 * i;
            float e = expf(scores[idx] - mx);
            scores[idx] = e;
            sum += e;
        }
#pragma unroll
        for (int o = 16; o > 0; o >>= 1)
            sum += __shfl_xor_sync(0xffffffffu, sum, o);
        if (l == 0) invs[h] = 1.f / sum;
    }
    __syncthreads();

    // u[h][j=t] = sum_k p[h][k] * seq_h[b][k][j]
#pragma unroll
    for (int h = 0; h < 4; h++) {
        float acc = 0.f;
#pragma unroll 8
        for (int k = 0; k < NS; k++)
            acc += scores[h * NS + k] * seqT[t * SEQ_PS + k];
        ubuf[h * NH + t] = acc * invs[h];
    }
    __syncthreads();

    // o1[t] = sum_m u[h][m] * Wv[m][t], h = t/32 ; context = o1 @ Wo
    {
        int h = t >> 5;
        float acc = 0.f;
#pragma unroll 8
        for (int m = 0; m < NH; m++)
            acc += ubuf[h * NH + m] * Wv[m * NH + t];
        o1buf[t] = acc;
    }
    __syncthreads();
    {
        float ctx = 0.f;
#pragma unroll 8
        for (int cix = 0; cix < NH; cix++)
            ctx += o1buf[cix] * Wo[cix * NH + t];
        catb[t] = ctx;
    }
    if (t < 13) catb[NH + t] = info[b * 13 + t];
    if (t < 3)  catb[141 + t] = action[b * 3 + t];
    __syncthreads();

    // twin MLP heads
    for (int kq = 0; kq < 2; kq++) {
        float v = q_b1[kq * NH + t];
#pragma unroll 8
        for (int cix = 0; cix < 144; cix++)
            v += catb[cix] * q_w1[(kq * 144 + cix) * NH + t];
        // layernorm over 128
        red[t] = v;
        red2[t] = v * v;
        __syncthreads();
        for (int st = 64; st > 0; st >>= 1) {
            if (t < st) { red[t] += red[t + st]; red2[t] += red2[t + st]; }
            __syncthreads();
        }
        float mu  = red[0] * (1.f / 128.f);
        float var = red2[0] * (1.f / 128.f) - mu * mu;
        float xn = (v - mu) * rsqrtf(var + 1e-5f) * q_gamma[kq * NH + t] +
                   q_beta[kq * NH + t];
        float g1 = gelu_exact(xn);
        __syncthreads();
        hvb[t] = g1;
        __syncthreads();
        float v2 = q_b2[kq * NH + t];
#pragma unroll 8
        for (int d = 0; d < NH; d++)
            v2 += hvb[d] * q_w2[(kq * NH + d) * NH + t];
        float g2 = gelu_exact(v2);
        red[t] = g2 * q_w3[kq * NH + t];
        __syncthreads();
        for (int st = 64; st > 0; st >>= 1) {
            if (t < st) red[t] += red[t + st];
            __syncthreads();
        }
        if (t == 0) out[kq * NB + b] = red[0] + q_b3[kq];
        __syncthreads();
    }
}

// ============ launch ============
extern "C" void kernel_launch(void* const* d_in, const int* in_sizes, int n_in,
                              void* d_out, int out_size) {
    const float* x      = (const float*)d_in[0];
    const float* action = (const float*)d_in[1];
    const float* info   = (const float*)d_in[2];
    const float* W_ih   = (const float*)d_in[3];
    const float* W_hh   = (const float*)d_in[4];
    const float* b_cell = (const float*)d_in[5];
    const float* Wq     = (const float*)d_in[6];
    const float* Wk     = (const float*)d_in[7];
    const float* Wv     = (const float*)d_in[8];
    const float* Wo     = (const float*)d_in[9];
    const float* q_w1   = (const float*)d_in[10];
    const float* q_b1   = (const float*)d_in[11];
    const float* q_gamma= (const float*)d_in[12];
    const float* q_beta = (const float*)d_in[13];
    const float* q_w2   = (const float*)d_in[14];
    const float* q_b2   = (const float*)d_in[15];
    const float* q_w3   = (const float*)d_in[16];
    const float* q_b3   = (const float*)d_in[17];
    float* out = (float*)d_out;

    const int scan_smem  = KHS * NH * 16 + 8 * NH * 8;                  // 204800
    const int final_smem = (NH * SEQ_PS + 4 * NS + 4 * NH + 4 * NH +
                            NH + NH + 144 + NH + NH + NH + 4) * 4;
    cudaFuncSetAttribute(k_scan, cudaFuncAttributeMaxDynamicSharedMemorySize,
                         scan_smem);
    cudaFuncSetAttribute(k_final, cudaFuncAttributeMaxDynamicSharedMemorySize,
                         final_smem);

    k_pack_whh<<<NH, NH>>>(W_hh);
    k_xpre<<<(NB * NS) / 16, 256>>>(x, W_ih, b_cell);
    k_scan<<<NB / 8, 256, scan_smem>>>();
    k_final<<<NB, 128, final_smem>>>(action, info, Wq, Wk, Wv, Wo,
                                     q_w1, q_b1, q_gamma, q_beta,
                                     q_w2, q_b2, q_w3, q_b3, out);
}

// round 4
// speedup vs baseline: 1.2314x; 1.2314x over previous
#include <cuda_runtime.h>
#include <cstdint>
#include <math.h>

#define NB 1024
#define NS 256
#define ND 64
#define NH 128
#define NG 512
#define KHS 96          // W_hh rows cached in smem

// -------- static scratch (no allocations allowed) --------
__device__ float      g_x_pre[(size_t)NB * NS * NG];   // 512 MB
__device__ float      g_seq_h[(size_t)NB * NS * NH];   // 128 MB
__device__ ulonglong2 g_WtHH[NH * NH];                 // gate-interleaved W_hh
__device__ float      g_rbuf[(size_t)NB * 4 * NH];     // per-b attention key vecs
__device__ float      g_U[(size_t)NB * 4 * NH];        // softmax-weighted h sums

// -------- packed f32x2 helpers --------
__device__ __forceinline__ unsigned long long pack2(float lo, float hi) {
    unsigned long long d;
    asm("mov.b64 %0, {%1, %2};" : "=l"(d) : "f"(lo), "f"(hi));
    return d;
}
__device__ __forceinline__ float2 unpack2(unsigned long long v) {
    float2 r;
    asm("mov.b64 {%0, %1}, %2;" : "=f"(r.x), "=f"(r.y) : "l"(v));
    return r;
}
__device__ __forceinline__ unsigned long long fma2(unsigned long long a,
                                                   unsigned long long b,
                                                   unsigned long long c) {
    unsigned long long d;
    asm("fma.rn.f32x2 %0, %1, %2, %3;" : "=l"(d) : "l"(a), "l"(b), "l"(c));
    return d;
}
__device__ __forceinline__ float gelu_exact(float x) {
    return 0.5f * x * (1.0f + erff(x * 0.7071067811865476f));
}

// ============ kernel 0: gate-interleave W_hh ============
__global__ void k_pack_whh(const float* __restrict__ W_hh) {
    int k = blockIdx.x, j = threadIdx.x;
    const float* w = W_hh + k * NG + j;
    g_WtHH[k * NH + j] =
        make_ulonglong2(pack2(w[0], w[NH]), pack2(w[2 * NH], w[3 * NH]));
}

// ============ kernel 1: x_pre = x @ W_ih + b_cell ============
__global__ void __launch_bounds__(256) k_xpre(const float* __restrict__ x,
                                              const float* __restrict__ W_ih,
                                              const float* __restrict__ b_cell) {
    __shared__ unsigned long long xs2[8][ND];
    int t = threadIdx.x;
    int row0 = blockIdx.x * 16;

    for (int idx = t; idx < 8 * ND; idx += 256) {
        int r2 = idx >> 6, d = idx & 63;
        xs2[r2][d] = pack2(x[(row0 + 2 * r2) * ND + d],
                           x[(row0 + 2 * r2 + 1) * ND + d]);
    }
    __syncthreads();

    int c0 = t, c1 = t + 256;
    unsigned long long acc0[8], acc1[8];
    unsigned long long b0d = pack2(b_cell[c0], b_cell[c0]);
    unsigned long long b1d = pack2(b_cell[c1], b_cell[c1]);
#pragma unroll
    for (int r2 = 0; r2 < 8; r2++) { acc0[r2] = b0d; acc1[r2] = b1d; }

#pragma unroll 8
    for (int d = 0; d < ND; d++) {
        float w0 = W_ih[d * NG + c0];
        float w1 = W_ih[d * NG + c1];
        unsigned long long w0d = pack2(w0, w0);
        unsigned long long w1d = pack2(w1, w1);
#pragma unroll
        for (int r2 = 0; r2 < 8; r2++) {
            unsigned long long xv = xs2[r2][d];
            acc0[r2] = fma2(xv, w0d, acc0[r2]);
            acc1[r2] = fma2(xv, w1d, acc1[r2]);
        }
    }
#pragma unroll
    for (int r2 = 0; r2 < 8; r2++) {
        float2 v0 = unpack2(acc0[r2]);
        float2 v1 = unpack2(acc1[r2]);
        int ra = row0 + 2 * r2, rb = ra + 1;
        g_x_pre[(size_t)ra * NG + c0] = v0.x;
        g_x_pre[(size_t)rb * NG + c0] = v0.y;
        g_x_pre[(size_t)ra * NG + c1] = v1.x;
        g_x_pre[(size_t)rb * NG + c1] = v1.y;
    }
}

// ============ kernel 2: sLSTM scan ============
// 128 CTAs x 8 batch rows, 128 threads; thread owns gate column j for 8 rows.
__global__ void __launch_bounds__(128, 1) k_scan() {
    extern __shared__ unsigned char smraw[];
    ulonglong2* WhhS = (ulonglong2*)smraw;                               // 196608 B
    unsigned long long* hbuf =
        (unsigned long long*)(smraw + (size_t)KHS * NH * 16);            // 2*8*128*8 B

    const int j  = threadIdx.x;
    const int b0 = blockIdx.x * 8;

    for (int idx = j; idx < KHS * NH; idx += 128) WhhS[idx] = g_WtHH[idx];
    for (int idx = j; idx < 2 * 8 * NH; idx += 128) hbuf[idx] = 0ull;

    float c[8], n[8];
#pragma unroll
    for (int r = 0; r < 8; r++) { c[r] = 0.f; n[r] = 1.f; }

    const float* xr[8];
#pragma unroll
    for (int r = 0; r < 8; r++)
        xr[r] = g_x_pre + (size_t)(b0 + r) * NS * NG + j;

    float xc[32], xn2[32];
#pragma unroll
    for (int r = 0; r < 8; r++)
#pragma unroll
        for (int g = 0; g < 4; g++) xc[r * 4 + g] = xr[r][g * NH];

    __syncthreads();

    int cur = 0;
    for (int s = 0; s < NS; ++s) {
        unsigned long long a01[8], a23[8];
#pragma unroll
        for (int r = 0; r < 8; r++) {
            a01[r] = pack2(xc[r * 4 + 0], xc[r * 4 + 1]);
            a23[r] = pack2(xc[r * 4 + 2], xc[r * 4 + 3]);
        }
        // prefetch next step's x_pre
        int sn = (s + 1 < NS) ? (s + 1) : s;
#pragma unroll
        for (int r = 0; r < 8; r++)
#pragma unroll
            for (int g = 0; g < 4; g++)
                xn2[r * 4 + g] = xr[r][(size_t)sn * NG + g * NH];

        const unsigned long long* hc = hbuf + cur * 8 * NH;

        // smem-cached W_hh rows
#pragma unroll 4
        for (int k = 0; k < KHS; k += 2) {
            ulonglong2 w0 = WhhS[k * NH + j];
            ulonglong2 w1 = WhhS[(k + 1) * NH + j];
#pragma unroll
            for (int r = 0; r < 8; r++) {
                ulonglong2 hp = *(const ulonglong2*)&hc[r * NH + k];
                a01[r] = fma2(hp.x, w0.x, a01[r]);
                a23[r] = fma2(hp.x, w0.y, a23[r]);
                a01[r] = fma2(hp.y, w1.x, a01[r]);
                a23[r] = fma2(hp.y, w1.y, a23[r]);
            }
        }
        // L2-streamed W_hh rows
#pragma unroll 8
        for (int k = KHS; k < NH; k += 2) {
            ulonglong2 w0 = g_WtHH[k * NH + j];
            ulonglong2 w1 = g_WtHH[(k + 1) * NH + j];
#pragma unroll
            for (int r = 0; r < 8; r++) {
                ulonglong2 hp = *(const ulonglong2*)&hc[r * NH + k];
                a01[r] = fma2(hp.x, w0.x, a01[r]);
                a23[r] = fma2(hp.x, w0.y, a23[r]);
                a01[r] = fma2(hp.y, w1.x, a01[r]);
                a23[r] = fma2(hp.y, w1.y, a23[r]);
            }
        }

        unsigned long long* hn = hbuf + (cur ^ 1) * 8 * NH;
#pragma unroll
        for (int r = 0; r < 8; r++) {
            float2 if_ = unpack2(a01[r]);
            float2 zo  = unpack2(a23[r]);
            float iv = expf(if_.x);
            float fv = 1.f / (1.f + expf(-if_.y));
            float zv = tanhf(zo.x);
            float ov = 1.f / (1.f + expf(-zo.y));
            c[r] = fv * c[r] + iv * zv;
            n[r] = fv * n[r] + iv;
            float h = ov * (c[r] / n[r]);
            hn[r * NH + j] = pack2(h, h);
            g_seq_h[((size_t)(b0 + r) * NS + s) * NH + j] = h;
        }
        __syncthreads();
        cur ^= 1;
#pragma unroll
        for (int i = 0; i < 32; i++) xc[i] = xn2[i];
    }
}

// ============ kernel 3: per-b key vectors rbuf = (Wk @ (h_last @ Wq)) / sqrt(32)
// grid 64, block 128, 16 b per CTA. Wq/Wk staged in smem.
#define PREP_NB 16
__global__ void __launch_bounds__(128) k_prep(const float* __restrict__ Wq,
                                              const float* __restrict__ Wk) {
    extern __shared__ float sm[];
    float* Wq_s = sm;                       // [128][128]
    float* Wk_s = Wq_s + NH * NH;           // [128][129] padded
    float* hl_s = Wk_s + NH * 129;          // [16][128]
    float* q_s  = hl_s + PREP_NB * NH;      // [16][128]

    const int t  = threadIdx.x;
    const int b0 = blockIdx.x * PREP_NB;

    for (int i = t; i < NH * NH; i += 128) Wq_s[i] = Wq[i];
    for (int i = t; i < NH * NH; i += 128) {
        int m = i >> 7, d = i & 127;
        Wk_s[m * 129 + d] = Wk[i];
    }
    for (int i = t; i < PREP_NB * NH; i += 128) {
        int bb = i >> 7, k = i & 127;
        hl_s[i] = g_seq_h[(((size_t)(b0 + bb) * NS) + (NS - 1)) * NH + k];
    }
    __syncthreads();

    for (int bb = 0; bb < PREP_NB; bb++) {
        float acc = 0.f;
#pragma unroll 8
        for (int k = 0; k < NH; k++)
            acc += hl_s[bb * NH + k] * Wq_s[k * NH + t];
        q_s[bb * NH + t] = acc;
    }
    __syncthreads();

    const float is32 = 0.17677669529663687f;
    int m = t;
    for (int bb = 0; bb < PREP_NB; bb++) {
#pragma unroll
        for (int h = 0; h < 4; h++) {
            float acc = 0.f;
#pragma unroll 8
            for (int d = 0; d < 32; d++)
                acc += Wk_s[m * 129 + h * 32 + d] * q_s[bb * NH + h * 32 + d];
            g_rbuf[((size_t)(b0 + bb) * 4 + h) * NH + m] = acc * is32;
        }
    }
}

// ============ kernel 4: streaming attention pass ============
// One CTA per b, 128 threads. Warp w owns s in [w*64, w*64+64).
// Single pass over seq_h: per s compute 4 head scores, exp (no max-sub:
// scores are O(0.1) bounded), accumulate U[h][m] and den[h].
__global__ void __launch_bounds__(128) k_attn() {
    __shared__ float Us[4 * 4 * NH];   // [w][h][m]
    __shared__ float dens[16];         // [w][h]

    const int t = threadIdx.x;
    const int w = t >> 5, l = t & 31;
    const int b = blockIdx.x;

    // per-lane rbuf values for its 4 m positions (m = 4l + c)
    float rbq[4][4];
#pragma unroll
    for (int h = 0; h < 4; h++)
#pragma unroll
        for (int cc = 0; cc < 4; cc++)
            rbq[h][cc] = g_rbuf[((size_t)b * 4 + h) * NH + 4 * l + cc];

    float uacc[4][4];
    float den[4];
#pragma unroll
    for (int h = 0; h < 4; h++) {
        den[h] = 0.f;
#pragma unroll
        for (int cc = 0; cc < 4; cc++) uacc[h][cc] = 0.f;
    }

    const float4* rowbase =
        (const float4*)(g_seq_h + ((size_t)b * NS) * NH) + l;

    for (int i = 0; i < 64; i++) {
        int s = w * 64 + i;
        float4 v = rowbase[(size_t)s * (NH / 4)];
        float p0 = v.x * rbq[0][0] + v.y * rbq[0][1] + v.z * rbq[0][2] + v.w * rbq[0][3];
        float p1 = v.x * rbq[1][0] + v.y * rbq[1][1] + v.z * rbq[1][2] + v.w * rbq[1][3];
        float p2 = v.x * rbq[2][0] + v.y * rbq[2][1] + v.z * rbq[2][2] + v.w * rbq[2][3];
        float p3 = v.x * rbq[3][0] + v.y * rbq[3][1] + v.z * rbq[3][2] + v.w * rbq[3][3];
#pragma unroll
        for (int o = 16; o > 0; o >>= 1) {
            p0 += __shfl_xor_sync(0xffffffffu, p0, o);
            p1 += __shfl_xor_sync(0xffffffffu, p1, o);
            p2 += __shfl_xor_sync(0xffffffffu, p2, o);
            p3 += __shfl_xor_sync(0xffffffffu, p3, o);
        }
        float e0 = expf(p0), e1 = expf(p1), e2 = expf(p2), e3 = expf(p3);
        den[0] += e0; den[1] += e1; den[2] += e2; den[3] += e3;
        uacc[0][0] += e0 * v.x; uacc[0][1] += e0 * v.y; uacc[0][2] += e0 * v.z; uacc[0][3] += e0 * v.w;
        uacc[1][0] += e1 * v.x; uacc[1][1] += e1 * v.y; uacc[1][2] += e1 * v.z; uacc[1][3] += e1 * v.w;
        uacc[2][0] += e2 * v.x; uacc[2][1] += e2 * v.y; uacc[2][2] += e2 * v.z; uacc[2][3] += e2 * v.w;
        uacc[3][0] += e3 * v.x; uacc[3][1] += e3 * v.y; uacc[3][2] += e3 * v.z; uacc[3][3] += e3 * v.w;
    }

#pragma unroll
    for (int h = 0; h < 4; h++)
#pragma unroll
        for (int cc = 0; cc < 4; cc++)
            Us[(w * 4 + h) * NH + 4 * l + cc] = uacc[h][cc];
    if (l == 0) {
#pragma unroll
        for (int h = 0; h < 4; h++) dens[w * 4 + h] = den[h];
    }
    __syncthreads();

#pragma unroll
    for (int g = 0; g < 4; g++) {
        int idx = g * NH + t;            // 0..511 -> (h = idx/128, m)
        int h = idx >> 7;
        float s = Us[idx] + Us[512 + idx] + Us[1024 + idx] + Us[1536 + idx];
        float dh = dens[h] + dens[4 + h] + dens[8 + h] + dens[12 + h];
        g_U[(size_t)b * 512 + idx] = s / dh;
    }
}

// ============ kernel 5: context + twin MLP heads ============
// 128 CTAs x 8 b, 128 threads. Weights staged in smem, reused across 8 b.
#define POST_NB 8
__global__ void __launch_bounds__(128) k_post(
    const float* __restrict__ action, const float* __restrict__ info,
    const float* __restrict__ Wv, const float* __restrict__ Wo,
    const float* __restrict__ q_w1, const float* __restrict__ q_b1,
    const float* __restrict__ q_gamma, const float* __restrict__ q_beta,
    const float* __restrict__ q_w2, const float* __restrict__ q_b2,
    const float* __restrict__ q_w3, const float* __restrict__ q_b3,
    float* __restrict__ out) {
    extern __shared__ float sm[];
    float* wbuf = sm;                       // up to 144*128 floats
    float* Ub   = wbuf + 144 * NH;          // [8][512]
    float* o1   = Ub + POST_NB * 512;       // [8][128]
    float* cat  = o1 + POST_NB * NH;        // [8][144]
    float* hv   = cat + POST_NB * 144;      // [8][128]
    float* mus  = hv + POST_NB * NH;        // [8]
    float* rvs  = mus + POST_NB;            // [8]

    const int t  = threadIdx.x;
    const int w  = t >> 5, l = t & 31;
    const int b0 = blockIdx.x * POST_NB;
    const int myh = t >> 5;

    for (int i = t; i < POST_NB * 512; i += 128)
        Ub[i] = g_U[(size_t)b0 * 512 + i];
    for (int i = t; i < NH * NH; i += 128) wbuf[i] = Wv[i];
    __syncthreads();

    // o1[bb][t] = sum_m Ub[bb][myh*128+m] * Wv[m][t]
    for (int bb = 0; bb < POST_NB; bb++) {
        float acc = 0.f;
#pragma unroll 8
        for (int m = 0; m < NH; m++)
            acc += Ub[bb * 512 + myh * NH + m] * wbuf[m * NH + t];
        o1[bb * NH + t] = acc;
    }
    __syncthreads();
    for (int i = t; i < NH * NH; i += 128) wbuf[i] = Wo[i];
    __syncthreads();
    for (int bb = 0; bb < POST_NB; bb++) {
        float acc = 0.f;
#pragma unroll 8
        for (int cix = 0; cix < NH; cix++)
            acc += o1[bb * NH + cix] * wbuf[cix * NH + t];
        cat[bb * 144 + t] = acc;
    }
    for (int i = t; i < POST_NB * 13; i += 128) {
        int bb = i / 13, d = i % 13;
        cat[bb * 144 + NH + d] = info[(b0 + bb) * 13 + d];
    }
    for (int i = t; i < POST_NB * 3; i += 128) {
        int bb = i / 3, d = i % 3;
        cat[bb * 144 + 141 + d] = action[(b0 + bb) * 3 + d];
    }
    __syncthreads();

    for (int kq = 0; kq < 2; kq++) {
        for (int i = t; i < 144 * NH; i += 128)
            wbuf[i] = q_w1[(size_t)kq * 144 * NH + i];
        float b1v = q_b1[kq * NH + t];
        float gav = q_gamma[kq * NH + t];
        float bev = q_beta[kq * NH + t];
        __syncthreads();

        float v[POST_NB];
        for (int bb = 0; bb < POST_NB; bb++) {
            float acc = b1v;
#pragma unroll 8
            for (int cix = 0; cix < 144; cix++)
                acc += cat[bb * 144 + cix] * wbuf[cix * NH + t];
            v[bb] = acc;
            hv[bb * NH + t] = acc;
        }
        __syncthreads();
        // LN stats: warp w handles bb = 2w, 2w+1
        for (int q = 0; q < 2; q++) {
            int bb = 2 * w + q;
            float s1 = hv[bb * NH + l] + hv[bb * NH + l + 32] +
                       hv[bb * NH + l + 64] + hv[bb * NH + l + 96];
            float x0 = hv[bb * NH + l], x1 = hv[bb * NH + l + 32],
                  x2 = hv[bb * NH + l + 64], x3 = hv[bb * NH + l + 96];
            float s2 = x0 * x0 + x1 * x1 + x2 * x2 + x3 * x3;
#pragma unroll
            for (int o = 16; o > 0; o >>= 1) {
                s1 += __shfl_xor_sync(0xffffffffu, s1, o);
                s2 += __shfl_xor_sync(0xffffffffu, s2, o);
            }
            if (l == 0) {
                float mu = s1 * (1.f / 128.f);
                float var = s2 * (1.f / 128.f) - mu * mu;
                mus[bb] = mu;
                rvs[bb] = rsqrtf(var + 1e-5f);
            }
        }
        __syncthreads();
        for (int bb = 0; bb < POST_NB; bb++) {
            float xn = (v[bb] - mus[bb]) * rvs[bb] * gav + bev;
            hv[bb * NH + t] = gelu_exact(xn);
        }
        __syncthreads();

        for (int i = t; i < NH * NH; i += 128)
            wbuf[i] = q_w2[(size_t)kq * NH * NH + i];
        float b2v = q_b2[kq * NH + t];
        float w3v = q_w3[kq * NH + t];
        __syncthreads();

        float g2v[POST_NB];
        for (int bb = 0; bb < POST_NB; bb++) {
            float acc = b2v;
#pragma unroll 8
            for (int d = 0; d < NH; d++)
                acc += hv[bb * NH + d] * wbuf[d * NH + t];
            g2v[bb] = gelu_exact(acc) * w3v;
        }
        __syncthreads();
        for (int bb = 0; bb < POST_NB; bb++)
            hv[bb * NH + t] = g2v[bb];
        __syncthreads();
        for (int q = 0; q < 2; q++) {
            int bb = 2 * w + q;
            float s1 = hv[bb * NH + l] + hv[bb * NH + l + 32] +
                       hv[bb * NH + l + 64] + hv[bb * NH + l + 96];
#pragma unroll
            for (int o = 16; o > 0; o >>= 1)
                s1 += __shfl_xor_sync(0xffffffffu, s1, o);
            if (l == 0)
                out[kq * NB + b0 + bb] = s1 + q_b3[kq];
        }
        __syncthreads();
    }
}

// ============ launch ============
extern "C" void kernel_launch(void* const* d_in, const int* in_sizes, int n_in,
                              void* d_out, int out_size) {
    const float* x      = (const float*)d_in[0];
    const float* action = (const float*)d_in[1];
    const float* info   = (const float*)d_in[2];
    const float* W_ih   = (const float*)d_in[3];
    const float* W_hh   = (const float*)d_in[4];
    const float* b_cell = (const float*)d_in[5];
    const float* Wq     = (const float*)d_in[6];
    const float* Wk     = (const float*)d_in[7];
    const float* Wv     = (const float*)d_in[8];
    const float* Wo     = (const float*)d_in[9];
    const float* q_w1   = (const float*)d_in[10];
    const float* q_b1   = (const float*)d_in[11];
    const float* q_gamma= (const float*)d_in[12];
    const float* q_beta = (const float*)d_in[13];
    const float* q_w2   = (const float*)d_in[14];
    const float* q_b2   = (const float*)d_in[15];
    const float* q_w3   = (const float*)d_in[16];
    const float* q_b3   = (const float*)d_in[17];
    float* out = (float*)d_out;

    const int scan_smem = KHS * NH * 16 + 2 * 8 * NH * 8;               // 212992
    const int prep_smem = (NH * NH + NH * 129 + 2 * PREP_NB * NH) * 4;  // 147968
    const int post_smem = (144 * NH + POST_NB * 512 + POST_NB * NH +
                           POST_NB * 144 + POST_NB * NH + 2 * POST_NB) * 4;
    cudaFuncSetAttribute(k_scan, cudaFuncAttributeMaxDynamicSharedMemorySize,
                         scan_smem);
    cudaFuncSetAttribute(k_prep, cudaFuncAttributeMaxDynamicSharedMemorySize,
                         prep_smem);
    cudaFuncSetAttribute(k_post, cudaFuncAttributeMaxDynamicSharedMemorySize,
                         post_smem);

    k_pack_whh<<<NH, NH>>>(W_hh);
    k_xpre<<<(NB * NS) / 16, 256>>>(x, W_ih, b_cell);
    k_scan<<<NB / 8, 128, scan_smem>>>();
    k_prep<<<NB / PREP_NB, 128, prep_smem>>>(Wq, Wk);
    k_attn<<<NB, 128>>>();
    k_post<<<NB / POST_NB, 128, post_smem>>>(action, info, Wv, Wo,
                                             q_w1, q_b1, q_gamma, q_beta,
                                             q_w2, q_b2, q_w3, q_b3, out);
}

// round 6
// speedup vs baseline: 1.4271x; 1.1589x over previous
#include <cuda_runtime.h>
#include <cstdint>
#include <math.h>

#define NB 1024
#define NS 256
#define ND 64
#define NH 128
#define NG 512
#define KHS 96          // W_hh rows cached in smem

// -------- static scratch (no allocations allowed) --------
__device__ float      g_x_pre[(size_t)NB * NS * NG];   // 512 MB
__device__ float      g_seq_h[(size_t)NB * NS * NH];   // 128 MB
__device__ ulonglong2 g_WtHH[NH * NH];                 // gate-interleaved W_hh
__device__ float      g_U[(size_t)NB * 4 * NH];        // softmax-weighted h sums

// -------- packed f32x2 helpers --------
__device__ __forceinline__ unsigned long long pack2(float lo, float hi) {
    unsigned long long d;
    asm("mov.b64 %0, {%1, %2};" : "=l"(d) : "f"(lo), "f"(hi));
    return d;
}
__device__ __forceinline__ float2 unpack2(unsigned long long v) {
    float2 r;
    asm("mov.b64 {%0, %1}, %2;" : "=f"(r.x), "=f"(r.y) : "l"(v));
    return r;
}
__device__ __forceinline__ unsigned long long fma2(unsigned long long a,
                                                   unsigned long long b,
                                                   unsigned long long c) {
    unsigned long long d;
    asm("fma.rn.f32x2 %0, %1, %2, %3;" : "=l"(d) : "l"(a), "l"(b), "l"(c));
    return d;
}
__device__ __forceinline__ float gelu_exact(float x) {
    return 0.5f * x * (1.0f + erff(x * 0.7071067811865476f));
}
__device__ __forceinline__ float fsigmoid(float x) {
    return __fdividef(1.f, 1.f + __expf(-x));
}
__device__ __forceinline__ float ftanh(float x) {
    return __fdividef(2.f, 1.f + __expf(-2.f * x)) - 1.f;
}

// ============ kernel 0: gate-interleave W_hh ============
__global__ void k_pack_whh(const float* __restrict__ W_hh) {
    int k = blockIdx.x, j = threadIdx.x;
    const float* w = W_hh + k * NG + j;
    g_WtHH[k * NH + j] =
        make_ulonglong2(pack2(w[0], w[NH]), pack2(w[2 * NH], w[3 * NH]));
}

// ============ kernel 1: x_pre = x @ W_ih + b_cell ============
__global__ void __launch_bounds__(256) k_xpre(const float* __restrict__ x,
                                              const float* __restrict__ W_ih,
                                              const float* __restrict__ b_cell) {
    __shared__ unsigned long long xs2[8][ND];
    int t = threadIdx.x;
    int row0 = blockIdx.x * 16;

    for (int idx = t; idx < 8 * ND; idx += 256) {
        int r2 = idx >> 6, d = idx & 63;
        xs2[r2][d] = pack2(x[(row0 + 2 * r2) * ND + d],
                           x[(row0 + 2 * r2 + 1) * ND + d]);
    }
    __syncthreads();

    int c0 = t, c1 = t + 256;
    unsigned long long acc0[8], acc1[8];
    unsigned long long b0d = pack2(b_cell[c0], b_cell[c0]);
    unsigned long long b1d = pack2(b_cell[c1], b_cell[c1]);
#pragma unroll
    for (int r2 = 0; r2 < 8; r2++) { acc0[r2] = b0d; acc1[r2] = b1d; }

#pragma unroll 8
    for (int d = 0; d < ND; d++) {
        float w0 = W_ih[d * NG + c0];
        float w1 = W_ih[d * NG + c1];
        unsigned long long w0d = pack2(w0, w0);
        unsigned long long w1d = pack2(w1, w1);
#pragma unroll
        for (int r2 = 0; r2 < 8; r2++) {
            unsigned long long xv = xs2[r2][d];
            acc0[r2] = fma2(xv, w0d, acc0[r2]);
            acc1[r2] = fma2(xv, w1d, acc1[r2]);
        }
    }
#pragma unroll
    for (int r2 = 0; r2 < 8; r2++) {
        float2 v0 = unpack2(acc0[r2]);
        float2 v1 = unpack2(acc1[r2]);
        int ra = row0 + 2 * r2, rb = ra + 1;
        g_x_pre[(size_t)ra * NG + c0] = v0.x;
        g_x_pre[(size_t)rb * NG + c0] = v0.y;
        g_x_pre[(size_t)ra * NG + c1] = v1.x;
        g_x_pre[(size_t)rb * NG + c1] = v1.y;
    }
}

// ============ kernel 2: sLSTM scan ============
// 128 CTAs x 8 batch rows, 128 threads; thread owns gate column j for 8 rows.
__global__ void __launch_bounds__(128, 1) k_scan() {
    extern __shared__ unsigned char smraw[];
    ulonglong2* WhhS = (ulonglong2*)smraw;                               // 196608 B
    unsigned long long* hbuf =
        (unsigned long long*)(smraw + (size_t)KHS * NH * 16);            // 2*8*128*8 B

    const int j  = threadIdx.x;
    const int b0 = blockIdx.x * 8;

    for (int idx = j; idx < KHS * NH; idx += 128) WhhS[idx] = g_WtHH[idx];
    for (int idx = j; idx < 2 * 8 * NH; idx += 128) hbuf[idx] = 0ull;

    float c[8], n[8];
#pragma unroll
    for (int r = 0; r < 8; r++) { c[r] = 0.f; n[r] = 1.f; }

    const float* xr[8];
#pragma unroll
    for (int r = 0; r < 8; r++)
        xr[r] = g_x_pre + (size_t)(b0 + r) * NS * NG + j;

    float xc[32], xn2[32];
#pragma unroll
    for (int r = 0; r < 8; r++)
#pragma unroll
        for (int g = 0; g < 4; g++) xc[r * 4 + g] = xr[r][g * NH];

    __syncthreads();

    int cur = 0;
    for (int s = 0; s < NS; ++s) {
        unsigned long long a01[8], a23[8];
#pragma unroll
        for (int r = 0; r < 8; r++) {
            a01[r] = pack2(xc[r * 4 + 0], xc[r * 4 + 1]);
            a23[r] = pack2(xc[r * 4 + 2], xc[r * 4 + 3]);
        }
        // prefetch next step's x_pre
        int sn = (s + 1 < NS) ? (s + 1) : s;
#pragma unroll
        for (int r = 0; r < 8; r++)
#pragma unroll
            for (int g = 0; g < 4; g++)
                xn2[r * 4 + g] = xr[r][(size_t)sn * NG + g * NH];

        const unsigned long long* hc = hbuf + cur * 8 * NH;

        // smem-cached W_hh rows
#pragma unroll 4
        for (int k = 0; k < KHS; k += 2) {
            ulonglong2 w0 = WhhS[k * NH + j];
            ulonglong2 w1 = WhhS[(k + 1) * NH + j];
#pragma unroll
            for (int r = 0; r < 8; r++) {
                ulonglong2 hp = *(const ulonglong2*)&hc[r * NH + k];
                a01[r] = fma2(hp.x, w0.x, a01[r]);
                a23[r] = fma2(hp.x, w0.y, a23[r]);
                a01[r] = fma2(hp.y, w1.x, a01[r]);
                a23[r] = fma2(hp.y, w1.y, a23[r]);
            }
        }
        // L2-streamed W_hh rows
#pragma unroll 8
        for (int k = KHS; k < NH; k += 2) {
            ulonglong2 w0 = g_WtHH[k * NH + j];
            ulonglong2 w1 = g_WtHH[(k + 1) * NH + j];
#pragma unroll
            for (int r = 0; r < 8; r++) {
                ulonglong2 hp = *(const ulonglong2*)&hc[r * NH + k];
                a01[r] = fma2(hp.x, w0.x, a01[r]);
                a23[r] = fma2(hp.x, w0.y, a23[r]);
                a01[r] = fma2(hp.y, w1.x, a01[r]);
                a23[r] = fma2(hp.y, w1.y, a23[r]);
            }
        }

        unsigned long long* hn = hbuf + (cur ^ 1) * 8 * NH;
#pragma unroll
        for (int r = 0; r < 8; r++) {
            float2 if_ = unpack2(a01[r]);
            float2 zo  = unpack2(a23[r]);
            float iv = __expf(if_.x);
            float fv = fsigmoid(if_.y);
            float zv = ftanh(zo.x);
            float ov = fsigmoid(zo.y);
            c[r] = fv * c[r] + iv * zv;
            n[r] = fv * n[r] + iv;
            float h = ov * __fdividef(c[r], n[r]);
            hn[r * NH + j] = pack2(h, h);
            g_seq_h[((size_t)(b0 + r) * NS + s) * NH + j] = h;
        }
        __syncthreads();
        cur ^= 1;
#pragma unroll
        for (int i = 0; i < 32; i++) xc[i] = xn2[i];
    }
}

// ============ kernel 3: fused qlast/rbuf + streaming attention pass ============
// One CTA per b, 128 threads. Computes q_last = h_last @ Wq, then per-head key
// vectors rbuf[h][m] = (Wk[m][h*32:]. q_last[h*32:]) / sqrt(32), then one
// streaming pass over seq_h accumulating U[h][m] and den[h].
__global__ void __launch_bounds__(128) k_attn(const float* __restrict__ Wq,
                                              const float* __restrict__ Wk) {
    __shared__ float hl[NH];
    __shared__ float ql[NH];
    __shared__ float rb[4 * NH];
    __shared__ float Us[4 * 4 * NH];   // [w][h][m]
    __shared__ float dens[16];         // [w][h]

    const int t = threadIdx.x;
    const int w = t >> 5, l = t & 31;
    const int b = blockIdx.x;

    hl[t] = g_seq_h[(((size_t)b * NS) + (NS - 1)) * NH + t];
    __syncthreads();

    // q_last[t] = sum_k hl[k] * Wq[k][t]
    {
        float acc = 0.f;
#pragma unroll 8
        for (int k = 0; k < NH; k++)
            acc += hl[k] * Wq[k * NH + t];
        ql[t] = acc;
    }
    __syncthreads();

    // rbuf[h][m=t] = is32 * sum_d Wk[t][h*32+d] * ql[h*32+d]
    const float is32 = 0.17677669529663687f;
    {
        const float4* wrow = (const float4*)(Wk + t * NH);
#pragma unroll
        for (int h = 0; h < 4; h++) {
            float acc = 0.f;
#pragma unroll
            for (int q4 = 0; q4 < 8; q4++) {
                float4 wv = wrow[h * 8 + q4];
                int d0 = h * 32 + q4 * 4;
                acc += wv.x * ql[d0] + wv.y * ql[d0 + 1] +
                       wv.z * ql[d0 + 2] + wv.w * ql[d0 + 3];
            }
            rb[h * NH + t] = acc * is32;
        }
    }
    __syncthreads();

    // per-lane rbuf values for its 4 m positions (m = 4l + cc)
    float rbq[4][4];
#pragma unroll
    for (int h = 0; h < 4; h++)
#pragma unroll
        for (int cc = 0; cc < 4; cc++)
            rbq[h][cc] = rb[h * NH + 4 * l + cc];

    float uacc[4][4];
    float den[4];
#pragma unroll
    for (int h = 0; h < 4; h++) {
        den[h] = 0.f;
#pragma unroll
        for (int cc = 0; cc < 4; cc++) uacc[h][cc] = 0.f;
    }

    const float4* rowbase =
        (const float4*)(g_seq_h + ((size_t)b * NS) * NH) + l;

    for (int i = 0; i < 64; i++) {
        int s = w * 64 + i;
        float4 v = rowbase[(size_t)s * (NH / 4)];
        float p0 = v.x * rbq[0][0] + v.y * rbq[0][1] + v.z * rbq[0][2] + v.w * rbq[0][3];
        float p1 = v.x * rbq[1][0] + v.y * rbq[1][1] + v.z * rbq[1][2] + v.w * rbq[1][3];
        float p2 = v.x * rbq[2][0] + v.y * rbq[2][1] + v.z * rbq[2][2] + v.w * rbq[2][3];
        float p3 = v.x * rbq[3][0] + v.y * rbq[3][1] + v.z * rbq[3][2] + v.w * rbq[3][3];
#pragma unroll
        for (int o = 16; o > 0; o >>= 1) {
            p0 += __shfl_xor_sync(0xffffffffu, p0, o);
            p1 += __shfl_xor_sync(0xffffffffu, p1, o);
            p2 += __shfl_xor_sync(0xffffffffu, p2, o);
            p3 += __shfl_xor_sync(0xffffffffu, p3, o);
        }
        float e0 = __expf(p0), e1 = __expf(p1), e2 = __expf(p2), e3 = __expf(p3);
        den[0] += e0; den[1] += e1; den[2] += e2; den[3] += e3;
        uacc[0][0] += e0 * v.x; uacc[0][1] += e0 * v.y; uacc[0][2] += e0 * v.z; uacc[0][3] += e0 * v.w;
        uacc[1][0] += e1 * v.x; uacc[1][1] += e1 * v.y; uacc[1][2] += e1 * v.z; uacc[1][3] += e1 * v.w;
        uacc[2][0] += e2 * v.x; uacc[2][1] += e2 * v.y; uacc[2][2] += e2 * v.z; uacc[2][3] += e2 * v.w;
        uacc[3][0] += e3 * v.x; uacc[3][1] += e3 * v.y; uacc[3][2] += e3 * v.z; uacc[3][3] += e3 * v.w;
    }

#pragma unroll
    for (int h = 0; h < 4; h++)
#pragma unroll
        for (int cc = 0; cc < 4; cc++)
            Us[(w * 4 + h) * NH + 4 * l + cc] = uacc[h][cc];
    if (l == 0) {
#pragma unroll
        for (int h = 0; h < 4; h++) dens[w * 4 + h] = den[h];
    }
    __syncthreads();

#pragma unroll
    for (int g = 0; g < 4; g++) {
        int idx = g * NH + t;            // 0..511 -> (h = idx/128, m)
        int h = idx >> 7;
        float s = Us[idx] + Us[512 + idx] + Us[1024 + idx] + Us[1536 + idx];
        float dh = dens[h] + dens[4 + h] + dens[8 + h] + dens[12 + h];
        g_U[(size_t)b * 512 + idx] = __fdividef(s, dh);
    }
}

// ============ kernel 4: context + twin MLP heads ============
// 128 CTAs x 8 b, 128 threads. Weights staged in smem, reused across 8 b.
#define POST_NB 8
__global__ void __launch_bounds__(128) k_post(
    const float* __restrict__ action, const float* __restrict__ info,
    const float* __restrict__ Wv, const float* __restrict__ Wo,
    const float* __restrict__ q_w1, const float* __restrict__ q_b1,
    const float* __restrict__ q_gamma, const float* __restrict__ q_beta,
    const float* __restrict__ q_w2, const float* __restrict__ q_b2,
    const float* __restrict__ q_w3, const float* __restrict__ q_b3,
    float* __restrict__ out) {
    extern __shared__ float sm[];
    float* wbuf = sm;                       // up to 144*128 floats
    float* Ub   = wbuf + 144 * NH;          // [8][512]
    float* o1   = Ub + POST_NB * 512;       // [8][128]
    float* cat  = o1 + POST_NB * NH;        // [8][144]
    float* hv   = cat + POST_NB * 144;      // [8][128]
    float* mus  = hv + POST_NB * NH;        // [8]
    float* rvs  = mus + POST_NB;            // [8]

    const int t  = threadIdx.x;
    const int w  = t >> 5, l = t & 31;
    const int b0 = blockIdx.x * POST_NB;
    const int myh = t >> 5;

    for (int i = t; i < POST_NB * 512; i += 128)
        Ub[i] = g_U[(size_t)b0 * 512 + i];
    for (int i = t; i < NH * NH; i += 128) wbuf[i] = Wv[i];
    __syncthreads();

    for (int bb = 0; bb < POST_NB; bb++) {
        float acc = 0.f;
#pragma unroll 8
        for (int m = 0; m < NH; m++)
            acc += Ub[bb * 512 + myh * NH + m] * wbuf[m * NH + t];
        o1[bb * NH + t] = acc;
    }
    __syncthreads();
    for (int i = t; i < NH * NH; i += 128) wbuf[i] = Wo[i];
    __syncthreads();
    for (int bb = 0; bb < POST_NB; bb++) {
        float acc = 0.f;
#pragma unroll 8
        for (int cix = 0; cix < NH; cix++)
            acc += o1[bb * NH + cix] * wbuf[cix * NH + t];
        cat[bb * 144 + t] = acc;
    }
    for (int i = t; i < POST_NB * 13; i += 128) {
        int bb = i / 13, d = i % 13;
        cat[bb * 144 + NH + d] = info[(b0 + bb) * 13 + d];
    }
    for (int i = t; i < POST_NB * 3; i += 128) {
        int bb = i / 3, d = i % 3;
        cat[bb * 144 + 141 + d] = action[(b0 + bb) * 3 + d];
    }
    __syncthreads();

    for (int kq = 0; kq < 2; kq++) {
        for (int i = t; i < 144 * NH; i += 128)
            wbuf[i] = q_w1[(size_t)kq * 144 * NH + i];
        float b1v = q_b1[kq * NH + t];
        float gav = q_gamma[kq * NH + t];
        float bev = q_beta[kq * NH + t];
        __syncthreads();

        float v[POST_NB];
        for (int bb = 0; bb < POST_NB; bb++) {
            float acc = b1v;
#pragma unroll 8
            for (int cix = 0; cix < 144; cix++)
                acc += cat[bb * 144 + cix] * wbuf[cix * NH + t];
            v[bb] = acc;
            hv[bb * NH + t] = acc;
        }
        __syncthreads();
        for (int q = 0; q < 2; q++) {
            int bb = 2 * w + q;
            float x0 = hv[bb * NH + l], x1 = hv[bb * NH + l + 32],
                  x2 = hv[bb * NH + l + 64], x3 = hv[bb * NH + l + 96];
            float s1 = x0 + x1 + x2 + x3;
            float s2 = x0 * x0 + x1 * x1 + x2 * x2 + x3 * x3;
#pragma unroll
            for (int o = 16; o > 0; o >>= 1) {
                s1 += __shfl_xor_sync(0xffffffffu, s1, o);
                s2 += __shfl_xor_sync(0xffffffffu, s2, o);
            }
            if (l == 0) {
                float mu = s1 * (1.f / 128.f);
                float var = s2 * (1.f / 128.f) - mu * mu;
                mus[bb] = mu;
                rvs[bb] = rsqrtf(var + 1e-5f);
            }
        }
        __syncthreads();
        for (int bb = 0; bb < POST_NB; bb++) {
            float xn = (v[bb] - mus[bb]) * rvs[bb] * gav + bev;
            hv[bb * NH + t] = gelu_exact(xn);
        }
        __syncthreads();

        for (int i = t; i < NH * NH; i += 128)
            wbuf[i] = q_w2[(size_t)kq * NH * NH + i];
        float b2v = q_b2[kq * NH + t];
        float w3v = q_w3[kq * NH + t];
        __syncthreads();

        float g2v[POST_NB];
        for (int bb = 0; bb < POST_NB; bb++) {
            float acc = b2v;
#pragma unroll 8
            for (int d = 0; d < NH; d++)
                acc += hv[bb * NH + d] * wbuf[d * NH + t];
            g2v[bb] = gelu_exact(acc) * w3v;
        }
        __syncthreads();
        for (int bb = 0; bb < POST_NB; bb++)
            hv[bb * NH + t] = g2v[bb];
        __syncthreads();
        for (int q = 0; q < 2; q++) {
            int bb = 2 * w + q;
            float s1 = hv[bb * NH + l] + hv[bb * NH + l + 32] +
                       hv[bb * NH + l + 64] + hv[bb * NH + l + 96];
#pragma unroll
            for (int o = 16; o > 0; o >>= 1)
                s1 += __shfl_xor_sync(0xffffffffu, s1, o);
            if (l == 0)
                out[kq * NB + b0 + bb] = s1 + q_b3[kq];
        }
        __syncthreads();
    }
}

// ============ launch ============
extern "C" void kernel_launch(void* const* d_in, const int* in_sizes, int n_in,
                              void* d_out, int out_size) {
    const float* x      = (const float*)d_in[0];
    const float* action = (const float*)d_in[1];
    const float* info   = (const float*)d_in[2];
    const float* W_ih   = (const float*)d_in[3];
    const float* W_hh   = (const float*)d_in[4];
    const float* b_cell = (const float*)d_in[5];
    const float* Wq     = (const float*)d_in[6];
    const float* Wk     = (const float*)d_in[7];
    const float* Wv     = (const float*)d_in[8];
    const float* Wo     = (const float*)d_in[9];
    const float* q_w1   = (const float*)d_in[10];
    const float* q_b1   = (const float*)d_in[11];
    const float* q_gamma= (const float*)d_in[12];
    const float* q_beta = (const float*)d_in[13];
    const float* q_w2   = (const float*)d_in[14];
    const float* q_b2   = (const float*)d_in[15];
    const float* q_w3   = (const float*)d_in[16];
    const float* q_b3   = (const float*)d_in[17];
    float* out = (float*)d_out;

    const int scan_smem = KHS * NH * 16 + 2 * 8 * NH * 8;
    const int post_smem = (144 * NH + POST_NB * 512 + POST_NB * NH +
                           POST_NB * 144 + POST_NB * NH + 2 * POST_NB) * 4;
    cudaFuncSetAttribute(k_scan, cudaFuncAttributeMaxDynamicSharedMemorySize,
                         scan_smem);
    cudaFuncSetAttribute(k_post, cudaFuncAttributeMaxDynamicSharedMemorySize,
                         post_smem);

    k_pack_whh<<<NH, NH>>>(W_hh);
    k_xpre<<<(NB * NS) / 16, 256>>>(x, W_ih, b_cell);
    k_scan<<<NB / 8, 128, scan_smem>>>();
    k_attn<<<NB, 128>>>(Wq, Wk);
    k_post<<<NB / POST_NB, 128, post_smem>>>(action, info, Wv, Wo,
                                             q_w1, q_b1, q_gamma, q_beta,
                                             q_w2, q_b2, q_w3, q_b3, out);
}